// round 8
// baseline (speedup 1.0000x reference)
#include <cuda_runtime.h>

#define NS   50000
#define NT   50000
#define NN   100000
#define HN   50000
#define D    128
#define NEG  0.2f
#define RB   24          // GEMM rows per block

// ---------------- scratch (device globals) ----------------------------------
__device__ float    g_x[(size_t)NN * D];
__device__ float    g_agg[(size_t)HN * D];
__device__ float    g_as1[NN], g_ad1[NN], g_as2[NN], g_ad2[NN];
__device__ float    g_w1s[D], g_w1d[D], g_w2s[D], g_w2d[D];
__device__ float    g_denom[HN];
__device__ int      g_is64;

__device__ __forceinline__ float lrelu(float v) { return v >= 0.f ? v : NEG * v; }

__device__ __forceinline__ void ffma2(unsigned long long& acc,
                                      unsigned long long a, unsigned long long b) {
    asm("fma.rn.f32x2 %0, %1, %2, %0;" : "+l"(acc) : "l"(a), "l"(b));
}

// ---------------- index width detection -------------------------------------
__global__ void k_detect(const int* __restrict__ p) {
    if (threadIdx.x == 0) {
        int all0 = 1;
        #pragma unroll
        for (int i = 1; i < 128; i += 2) all0 &= (p[i] == 0);
        g_is64 = all0;
    }
}

// ---------------- wv = W^T @ a ----------------------------------------------
__global__ void k_wvec(const float* __restrict__ W1, const float* __restrict__ a1s,
                       const float* __restrict__ a1d,
                       const float* __restrict__ W2, const float* __restrict__ a2s,
                       const float* __restrict__ a2d) {
    int j = threadIdx.x;
    float s1 = 0.f, d1 = 0.f, s2 = 0.f, d2 = 0.f;
    for (int k = 0; k < D; k++) {
        float w1 = W1[k * D + j], w2 = W2[k * D + j];
        s1 = fmaf(w1, a1s[k], s1); d1 = fmaf(w1, a1d[k], d1);
        s2 = fmaf(w2, a2s[k], s2); d2 = fmaf(w2, a2d[k], d2);
    }
    g_w1s[j] = s1; g_w1d[j] = d1; g_w2s[j] = s2; g_w2d[j] = d2;
}

// ---------------- FFMA2 GEMM: out[r,k] = act(bias[k] + (in[r]*scale[r]) . W[k,:])
// 128 threads (one output column each), RB rows per block, f32x2 packed over K.
__global__ __launch_bounds__(128) void k_gemm(
    const float* __restrict__ in, const float* __restrict__ W,
    const float* __restrict__ bias, const float* __restrict__ denom,
    float* __restrict__ out, int relu, int nrows)
{
    __shared__ float      xs[RB * 128];       // 12 KB
    __shared__ ulonglong2 Wq[8 * 128];        // 16 KB: one K-quarter of W, paired

    const int k = threadIdx.x;
    const int row0 = blockIdx.x * RB;

    // load x tile (scaled by 1/(denom+eps) when aggregating)
    for (int t = k; t < RB * 128; t += 128) {
        int r = t >> 7;
        int gr = row0 + r;
        float v = 0.f;
        if (gr < nrows) {
            v = in[(size_t)gr * D + (t & 127)];
            if (denom) v *= 1.0f / (denom[gr] + 1e-16f);
        }
        xs[t] = v;
    }

    unsigned long long acc[RB];
    #pragma unroll
    for (int r = 0; r < RB; r++) acc[r] = 0ull;

    const ulonglong2* xs2 = (const ulonglong2*)xs;   // [row][kd-chunk of 4]

    for (int q = 0; q < 4; q++) {                    // K quarters of 32
        __syncthreads();
        // stage W[:, q*32 : q*32+32) as f32x2 pairs, column-fastest
        #pragma unroll
        for (int i = 0; i < 8; i++) {
            int lin = i * 128 + k;
            int col = lin >> 3;                       // output column 0..127
            int c   = lin & 7;                        // 4-kd chunk within quarter
            float4 f = *(const float4*)(W + col * D + q * 32 + c * 4);
            ulonglong2 u;
            u.x = ((unsigned long long)__float_as_uint(f.y) << 32) | __float_as_uint(f.x);
            u.y = ((unsigned long long)__float_as_uint(f.w) << 32) | __float_as_uint(f.z);
            Wq[c * 128 + col] = u;
        }
        __syncthreads();

        #pragma unroll
        for (int c = 0; c < 8; c++) {
            ulonglong2 w2 = Wq[c * 128 + k];
            #pragma unroll
            for (int r = 0; r < RB; r++) {
                ulonglong2 x2 = xs2[r * 32 + q * 8 + c];
                ffma2(acc[r], x2.x, w2.x);
                ffma2(acc[r], x2.y, w2.y);
            }
        }
    }

    float b = bias ? bias[k] : 0.f;
    #pragma unroll
    for (int r = 0; r < RB; r++) {
        int gr = row0 + r;
        if (gr < nrows) {
            float lo = __uint_as_float((unsigned)acc[r]);
            float hi = __uint_as_float((unsigned)(acc[r] >> 32));
            float v = lo + hi + b;
            if (relu) v = fmaxf(v, 0.f);
            out[(size_t)gr * D + k] = v;
        }
    }
}

// ---------------- attention logits: warp per node ---------------------------
__global__ void k_att() {
    int n = (blockIdx.x * blockDim.x + threadIdx.x) >> 5;
    int lane = threadIdx.x & 31;
    if (n >= NN) return;
    float4 xv = ((const float4*)g_x)[(size_t)n * 32 + lane];
    float4 w;
    w = ((const float4*)g_w1s)[lane];
    float p1 = xv.x * w.x + xv.y * w.y + xv.z * w.z + xv.w * w.w;
    w = ((const float4*)g_w1d)[lane];
    float p2 = xv.x * w.x + xv.y * w.y + xv.z * w.z + xv.w * w.w;
    w = ((const float4*)g_w2s)[lane];
    float p3 = xv.x * w.x + xv.y * w.y + xv.z * w.z + xv.w * w.w;
    w = ((const float4*)g_w2d)[lane];
    float p4 = xv.x * w.x + xv.y * w.y + xv.z * w.z + xv.w * w.w;
    #pragma unroll
    for (int off = 16; off; off >>= 1) {
        p1 += __shfl_down_sync(0xffffffffu, p1, off);
        p2 += __shfl_down_sync(0xffffffffu, p2, off);
        p3 += __shfl_down_sync(0xffffffffu, p3, off);
        p4 += __shfl_down_sync(0xffffffffu, p4, off);
    }
    if (lane == 0) { g_as1[n] = p1; g_ad1[n] = p2; g_as2[n] = p3; g_ad2[n] = p4; }
}

// ---------------- self-loop: initialize denom & agg (no max subtraction) ----
__global__ void k_self(int base, const float* __restrict__ as, const float* __restrict__ ad) {
    int i = (blockIdx.x * blockDim.x + threadIdx.x) >> 5;
    int lane = threadIdx.x & 31;
    if (i >= HN) return;
    int g = base + i;
    float w = __expf(lrelu(as[g] + ad[g]));
    if (lane == 0) g_denom[i] = w;
    float4 xv = ((const float4*)g_x)[(size_t)g * 32 + lane];
    ((float4*)g_agg)[(size_t)i * 32 + lane] =
        make_float4(xv.x * w, xv.y * w, xv.z * w, xv.w * w);
}

// ---------------- edge pass: denom + unnormalized aggregation (warp/edge) ---
__global__ void k_eagg(const void* __restrict__ idx, int sOff, int dOff, int E,
                       int sAdd, int dAdd, int base,
                       const float* __restrict__ as, const float* __restrict__ ad) {
    int e = (blockIdx.x * blockDim.x + threadIdx.x) >> 5;
    int lane = threadIdx.x & 31;
    if (e >= E) return;
    long long s, d;
    if (g_is64) {
        s = ((const long long*)idx)[sOff + e];
        d = ((const long long*)idx)[dOff + e];
    } else {
        s = ((const int*)idx)[sOff + e];
        d = ((const int*)idx)[dOff + e];
    }
    s += sAdd; d += dAdd;
    int di = (int)d - base;
    if ((unsigned)di >= (unsigned)HN) return;     // dst row never read -> dead edge
    float w = __expf(lrelu(as[s] + ad[d]));
    if (lane == 0) atomicAdd(&g_denom[di], w);
    float4 xv = ((const float4*)g_x)[(size_t)s * 32 + lane];
    atomicAdd(&((float4*)g_agg)[(size_t)di * 32 + lane],
              make_float4(xv.x * w, xv.y * w, xv.z * w, xv.w * w));
}

// ---------------- driver ------------------------------------------------------
extern "C" void kernel_launch(void* const* d_in, const int* in_sizes, int n_in,
                              void* d_out, int out_size) {
    const void*  edge   = d_in[0];
    const void*  paper  = d_in[1];
    const void*  author = d_in[2];
    const float* x_s = (const float*)d_in[3];
    const float* x_t = (const float*)d_in[4];
    const float* Ws  = (const float*)d_in[5];
    const float* bs  = (const float*)d_in[6];
    const float* Wt  = (const float*)d_in[7];
    const float* bt  = (const float*)d_in[8];
    const float* W1  = (const float*)d_in[9];
    const float* a1s = (const float*)d_in[10];
    const float* a1d = (const float*)d_in[11];
    const float* W2  = (const float*)d_in[12];
    const float* a2s = (const float*)d_in[13];
    const float* a2d = (const float*)d_in[14];
    float* out = (float*)d_out;

    const int E0 = in_sizes[0] / 2;
    const int E1 = in_sizes[1] / 2;
    const int E2 = in_sizes[2] / 2;

    float* gx;   cudaGetSymbolAddress((void**)&gx,  g_x);
    float* gagg; cudaGetSymbolAddress((void**)&gagg, g_agg);
    float *gas1, *gad1, *gas2, *gad2;
    cudaGetSymbolAddress((void**)&gas1, g_as1);
    cudaGetSymbolAddress((void**)&gad1, g_ad1);
    cudaGetSymbolAddress((void**)&gas2, g_as2);
    cudaGetSymbolAddress((void**)&gad2, g_ad2);
    float* gden; cudaGetSymbolAddress((void**)&gden, g_denom);

    const int GEMM_BLKS = (NS + RB - 1) / RB;
    const int TB = 256;
    const int WEB0 = (E0 * 32 + TB - 1) / TB;
    const int WEB1 = (E1 * 32 + TB - 1) / TB;
    const int WEB2 = (E2 * 32 + TB - 1) / TB;
    const int WNB  = (HN * 32 + TB - 1) / TB;
    const int ATTB = (NN * 32 + TB - 1) / TB;

    k_detect<<<1, 32>>>((const int*)edge);
    k_wvec<<<1, 128>>>(W1, a1s, a1d, W2, a2s, a2d);

    // x = [x_s@Ws^T+bs ; x_t@Wt^T+bt]
    k_gemm<<<GEMM_BLKS, 128>>>(x_s, Ws, bs, nullptr, gx, 0, NS);
    k_gemm<<<GEMM_BLKS, 128>>>(x_t, Wt, bt, nullptr, gx + (size_t)NS * D, 0, NT);

    k_att<<<ATTB, TB>>>();

    // ---- conv1: dst in [NS, NN) ----
    k_self<<<WNB, TB>>>(NS, gas1, gad1);
    k_eagg<<<WEB0, TB>>>(edge,   0,  E0, E0, 0,  NS, NS, gas1, gad1);
    k_eagg<<<WEB2, TB>>>(author, 0,  E2, E2, 0,  0,  NS, gas1, gad1);
    k_gemm<<<GEMM_BLKS, 128>>>(gagg, W1, nullptr, gden, out + (size_t)NS * D, 1, NS);

    // ---- conv2: dst in [0, NS) ----
    k_self<<<WNB, TB>>>(0, gas2, gad2);
    k_eagg<<<WEB0, TB>>>(edge,  E0, 0,  E0, NS, 0, 0, gas2, gad2);
    k_eagg<<<WEB1, TB>>>(paper, 0,  E1, E1, 0,  0, 0, gas2, gad2);
    k_gemm<<<GEMM_BLKS, 128>>>(gagg, W2, nullptr, gden, out, 1, NS);
}

// round 9
// speedup vs baseline: 1.4783x; 1.4783x over previous
#include <cuda_runtime.h>

#define NS   50000
#define NT   50000
#define NN   100000
#define HN   50000
#define D    128
#define NEG  0.2f

#define BM   128
#define BK   16

// ---------------- scratch (device globals) ----------------------------------
__device__ float    g_x[(size_t)NN * D];
__device__ float    g_agg[(size_t)HN * D];
__device__ float    g_as1[NN], g_ad1[NN], g_as2[NN], g_ad2[NN];
__device__ float    g_w1s[D], g_w1d[D], g_w2s[D], g_w2d[D];
__device__ float    g_denom[HN];
__device__ int      g_is64;

__device__ __forceinline__ float lrelu(float v) { return v >= 0.f ? v : NEG * v; }

__device__ __forceinline__ void ffma2(unsigned long long& acc,
                                      unsigned long long a, unsigned long long b) {
    asm("fma.rn.f32x2 %0, %1, %2, %0;" : "+l"(acc) : "l"(a), "l"(b));
}
__device__ __forceinline__ unsigned long long dup2(float a) {
    unsigned long long r;
    asm("mov.b64 %0, {%1, %1};" : "=l"(r) : "r"(__float_as_uint(a)));
    return r;
}

// ---------------- index width detection -------------------------------------
__global__ void k_detect(const int* __restrict__ p) {
    if (threadIdx.x == 0) {
        int all0 = 1;
        #pragma unroll
        for (int i = 1; i < 128; i += 2) all0 &= (p[i] == 0);
        g_is64 = all0;
    }
}

// ---------------- wv = W^T @ a ----------------------------------------------
__global__ void k_wvec(const float* __restrict__ W1, const float* __restrict__ a1s,
                       const float* __restrict__ a1d,
                       const float* __restrict__ W2, const float* __restrict__ a2s,
                       const float* __restrict__ a2d) {
    int j = threadIdx.x;
    float s1 = 0.f, d1 = 0.f, s2 = 0.f, d2 = 0.f;
    for (int k = 0; k < D; k++) {
        float w1 = W1[k * D + j], w2 = W2[k * D + j];
        s1 = fmaf(w1, a1s[k], s1); d1 = fmaf(w1, a1d[k], d1);
        s2 = fmaf(w2, a2s[k], s2); d2 = fmaf(w2, a2d[k], d2);
    }
    g_w1s[j] = s1; g_w1d[j] = d1; g_w2s[j] = s2; g_w2d[j] = d2;
}

// ---------------- register-tiled SGEMM (f32x2) -------------------------------
// out[r,c] = act(bias[c] + (in[r] * scale[r]) . W[c,:]),  W row-major [128,128]
// 256 threads, block tile 128 rows x 128 cols, thread tile 8x8.
__global__ __launch_bounds__(256, 2) void k_gemm(
    const float* __restrict__ in, const float* __restrict__ W,
    const float* __restrict__ bias, const float* __restrict__ denom,
    float* __restrict__ out, int relu, int nrows)
{
    __shared__ float As[BK][BM];    // A chunk, transposed: As[k][row]
    __shared__ float Bs[BK][128];   // W chunk, transposed: Bs[k][col]

    const int tid  = threadIdx.x;
    const int row0 = blockIdx.x * BM;
    const int tr   = (tid >> 4) << 3;   // thread row base within tile
    const int tc   = (tid & 15) << 3;   // thread col base

    unsigned long long acc[8][4];
    #pragma unroll
    for (int i = 0; i < 8; i++)
        #pragma unroll
        for (int j = 0; j < 4; j++) acc[i][j] = 0ull;

    for (int k0 = 0; k0 < D; k0 += BK) {
        __syncthreads();
        #pragma unroll
        for (int i = 0; i < 2; i++) {
            int lin = i * 256 + tid;         // 0..511
            int r   = lin >> 2;              // 0..127 (row for A, col for W)
            int jj  = (lin & 3) << 2;        // 0,4,8,12 within chunk
            // A (guarded, optional 1/denom scale)
            int gr = row0 + r;
            float4 v = make_float4(0.f, 0.f, 0.f, 0.f);
            if (gr < nrows) {
                v = *(const float4*)(in + (size_t)gr * D + k0 + jj);
                if (denom) {
                    float s = 1.0f / (denom[gr] + 1e-16f);
                    v.x *= s; v.y *= s; v.z *= s; v.w *= s;
                }
            }
            As[jj + 0][r] = v.x; As[jj + 1][r] = v.y;
            As[jj + 2][r] = v.z; As[jj + 3][r] = v.w;
            // W (always in range; c = r)
            float4 w = *(const float4*)(W + (size_t)r * D + k0 + jj);
            Bs[jj + 0][r] = w.x; Bs[jj + 1][r] = w.y;
            Bs[jj + 2][r] = w.z; Bs[jj + 3][r] = w.w;
        }
        __syncthreads();

        #pragma unroll
        for (int kk = 0; kk < BK; kk++) {
            float4 a0 = *(const float4*)&As[kk][tr];
            float4 a1 = *(const float4*)&As[kk][tr + 4];
            ulonglong2 w0 = *(const ulonglong2*)&Bs[kk][tc];
            ulonglong2 w1 = *(const ulonglong2*)&Bs[kk][tc + 4];
            float a[8] = {a0.x, a0.y, a0.z, a0.w, a1.x, a1.y, a1.z, a1.w};
            #pragma unroll
            for (int i = 0; i < 8; i++) {
                unsigned long long ap = dup2(a[i]);
                ffma2(acc[i][0], ap, w0.x);
                ffma2(acc[i][1], ap, w0.y);
                ffma2(acc[i][2], ap, w1.x);
                ffma2(acc[i][3], ap, w1.y);
            }
        }
    }

    float bcol[8];
    #pragma unroll
    for (int j = 0; j < 8; j++) bcol[j] = bias ? bias[tc + j] : 0.f;

    #pragma unroll
    for (int i = 0; i < 8; i++) {
        int gr = row0 + tr + i;
        if (gr >= nrows) continue;
        float o[8];
        #pragma unroll
        for (int j = 0; j < 4; j++) {
            o[2 * j + 0] = __uint_as_float((unsigned)acc[i][j]) + bcol[2 * j + 0];
            o[2 * j + 1] = __uint_as_float((unsigned)(acc[i][j] >> 32)) + bcol[2 * j + 1];
        }
        if (relu) {
            #pragma unroll
            for (int j = 0; j < 8; j++) o[j] = fmaxf(o[j], 0.f);
        }
        *(float4*)(out + (size_t)gr * D + tc)     = make_float4(o[0], o[1], o[2], o[3]);
        *(float4*)(out + (size_t)gr * D + tc + 4) = make_float4(o[4], o[5], o[6], o[7]);
    }
}

// ---------------- attention logits: warp per node ---------------------------
__global__ void k_att() {
    int n = (blockIdx.x * blockDim.x + threadIdx.x) >> 5;
    int lane = threadIdx.x & 31;
    if (n >= NN) return;
    float4 xv = ((const float4*)g_x)[(size_t)n * 32 + lane];
    float4 w;
    w = ((const float4*)g_w1s)[lane];
    float p1 = xv.x * w.x + xv.y * w.y + xv.z * w.z + xv.w * w.w;
    w = ((const float4*)g_w1d)[lane];
    float p2 = xv.x * w.x + xv.y * w.y + xv.z * w.z + xv.w * w.w;
    w = ((const float4*)g_w2s)[lane];
    float p3 = xv.x * w.x + xv.y * w.y + xv.z * w.z + xv.w * w.w;
    w = ((const float4*)g_w2d)[lane];
    float p4 = xv.x * w.x + xv.y * w.y + xv.z * w.z + xv.w * w.w;
    #pragma unroll
    for (int off = 16; off; off >>= 1) {
        p1 += __shfl_down_sync(0xffffffffu, p1, off);
        p2 += __shfl_down_sync(0xffffffffu, p2, off);
        p3 += __shfl_down_sync(0xffffffffu, p3, off);
        p4 += __shfl_down_sync(0xffffffffu, p4, off);
    }
    if (lane == 0) { g_as1[n] = p1; g_ad1[n] = p2; g_as2[n] = p3; g_ad2[n] = p4; }
}

// ---------------- self-loop: initialize denom & agg --------------------------
__global__ void k_self(int base, const float* __restrict__ as, const float* __restrict__ ad) {
    int i = (blockIdx.x * blockDim.x + threadIdx.x) >> 5;
    int lane = threadIdx.x & 31;
    if (i >= HN) return;
    int g = base + i;
    float w = __expf(lrelu(as[g] + ad[g]));
    if (lane == 0) g_denom[i] = w;
    float4 xv = ((const float4*)g_x)[(size_t)g * 32 + lane];
    ((float4*)g_agg)[(size_t)i * 32 + lane] =
        make_float4(xv.x * w, xv.y * w, xv.z * w, xv.w * w);
}

// ---------------- edge pass: denom + unnormalized aggregation (warp/edge) ---
__global__ void k_eagg(const void* __restrict__ idx, int sOff, int dOff, int E,
                       int sAdd, int dAdd, int base,
                       const float* __restrict__ as, const float* __restrict__ ad) {
    int e = (blockIdx.x * blockDim.x + threadIdx.x) >> 5;
    int lane = threadIdx.x & 31;
    if (e >= E) return;
    long long s, d;
    if (g_is64) {
        s = ((const long long*)idx)[sOff + e];
        d = ((const long long*)idx)[dOff + e];
    } else {
        s = ((const int*)idx)[sOff + e];
        d = ((const int*)idx)[dOff + e];
    }
    s += sAdd; d += dAdd;
    int di = (int)d - base;
    if ((unsigned)di >= (unsigned)HN) return;
    float w = __expf(lrelu(as[s] + ad[d]));
    if (lane == 0) atomicAdd(&g_denom[di], w);
    float4 xv = ((const float4*)g_x)[(size_t)s * 32 + lane];
    atomicAdd(&((float4*)g_agg)[(size_t)di * 32 + lane],
              make_float4(xv.x * w, xv.y * w, xv.z * w, xv.w * w));
}

// ---------------- driver ------------------------------------------------------
extern "C" void kernel_launch(void* const* d_in, const int* in_sizes, int n_in,
                              void* d_out, int out_size) {
    const void*  edge   = d_in[0];
    const void*  paper  = d_in[1];
    const void*  author = d_in[2];
    const float* x_s = (const float*)d_in[3];
    const float* x_t = (const float*)d_in[4];
    const float* Ws  = (const float*)d_in[5];
    const float* bs  = (const float*)d_in[6];
    const float* Wt  = (const float*)d_in[7];
    const float* bt  = (const float*)d_in[8];
    const float* W1  = (const float*)d_in[9];
    const float* a1s = (const float*)d_in[10];
    const float* a1d = (const float*)d_in[11];
    const float* W2  = (const float*)d_in[12];
    const float* a2s = (const float*)d_in[13];
    const float* a2d = (const float*)d_in[14];
    float* out = (float*)d_out;

    const int E0 = in_sizes[0] / 2;
    const int E1 = in_sizes[1] / 2;
    const int E2 = in_sizes[2] / 2;

    float* gx;   cudaGetSymbolAddress((void**)&gx,  g_x);
    float* gagg; cudaGetSymbolAddress((void**)&gagg, g_agg);
    float *gas1, *gad1, *gas2, *gad2;
    cudaGetSymbolAddress((void**)&gas1, g_as1);
    cudaGetSymbolAddress((void**)&gad1, g_ad1);
    cudaGetSymbolAddress((void**)&gas2, g_as2);
    cudaGetSymbolAddress((void**)&gad2, g_ad2);
    float* gden; cudaGetSymbolAddress((void**)&gden, g_denom);

    const int GEMM_BLKS = (NS + BM - 1) / BM;   // 391
    const int TB = 256;
    const int WEB0 = (E0 * 32 + TB - 1) / TB;
    const int WEB1 = (E1 * 32 + TB - 1) / TB;
    const int WEB2 = (E2 * 32 + TB - 1) / TB;
    const int WNB  = (HN * 32 + TB - 1) / TB;
    const int ATTB = (NN * 32 + TB - 1) / TB;

    k_detect<<<1, 32>>>((const int*)edge);
    k_wvec<<<1, 128>>>(W1, a1s, a1d, W2, a2s, a2d);

    // x = [x_s@Ws^T+bs ; x_t@Wt^T+bt]
    k_gemm<<<GEMM_BLKS, 256>>>(x_s, Ws, bs, nullptr, gx, 0, NS);
    k_gemm<<<GEMM_BLKS, 256>>>(x_t, Wt, bt, nullptr, gx + (size_t)NS * D, 0, NT);

    k_att<<<ATTB, TB>>>();

    // ---- conv1: dst in [NS, NN) ----
    k_self<<<WNB, TB>>>(NS, gas1, gad1);
    k_eagg<<<WEB0, TB>>>(edge,   0,  E0, E0, 0,  NS, NS, gas1, gad1);
    k_eagg<<<WEB2, TB>>>(author, 0,  E2, E2, 0,  0,  NS, gas1, gad1);
    k_gemm<<<GEMM_BLKS, 256>>>(gagg, W1, nullptr, gden, out + (size_t)NS * D, 1, NS);

    // ---- conv2: dst in [0, NS) ----
    k_self<<<WNB, TB>>>(0, gas2, gad2);
    k_eagg<<<WEB0, TB>>>(edge,  E0, 0,  E0, NS, 0, 0, gas2, gad2);
    k_eagg<<<WEB1, TB>>>(paper, 0,  E1, E1, 0,  0, 0, gas2, gad2);
    k_gemm<<<GEMM_BLKS, 256>>>(gagg, W2, nullptr, gden, out, 1, NS);
}

// round 10
// speedup vs baseline: 1.9525x; 1.3208x over previous
#include <cuda_runtime.h>

#define NS   50000
#define NT   50000
#define NN   100000
#define HN   50000
#define D    128
#define NEG  0.2f

#define BM   128
#define BK   16
#define EMAX 1050000

// ---------------- scratch (device globals) ----------------------------------
__device__ float g_x[(size_t)NN * D];
__device__ float g_agg1[(size_t)HN * D];
__device__ float g_agg2[(size_t)HN * D];
__device__ float g_as1[NN], g_ad1[NN], g_as2[NN], g_ad2[NN];
__device__ float g_w1s[D], g_w1d[D], g_w2s[D], g_w2d[D];
__device__ int   g_cnt[HN];
__device__ int   g_ptr[HN + 1];
__device__ int   g_pos[HN];
__device__ int2  g_edge[EMAX];
__device__ int   g_is64;

__device__ __forceinline__ float lrelu(float v) { return v >= 0.f ? v : NEG * v; }

__device__ __forceinline__ void ffma2(unsigned long long& acc,
                                      unsigned long long a, unsigned long long b) {
    asm("fma.rn.f32x2 %0, %1, %2, %0;" : "+l"(acc) : "l"(a), "l"(b));
}
__device__ __forceinline__ unsigned long long dup2(float a) {
    unsigned long long r;
    asm("mov.b64 %0, {%1, %1};" : "=l"(r) : "r"(__float_as_uint(a)));
    return r;
}

// ---------------- index width detection -------------------------------------
__global__ void k_detect(const int* __restrict__ p) {
    if (threadIdx.x == 0) {
        int all0 = 1;
        #pragma unroll
        for (int i = 1; i < 128; i += 2) all0 &= (p[i] == 0);
        g_is64 = all0;
    }
}

__device__ __forceinline__ void load_edge(const void* idx, int off, int e,
                                          long long& v) {
    if (g_is64) v = ((const long long*)idx)[off + e];
    else        v = ((const int*)idx)[off + e];
}

// ---------------- wv = W^T @ a ----------------------------------------------
__global__ void k_wvec(const float* __restrict__ W1, const float* __restrict__ a1s,
                       const float* __restrict__ a1d,
                       const float* __restrict__ W2, const float* __restrict__ a2s,
                       const float* __restrict__ a2d) {
    int j = threadIdx.x;
    float s1 = 0.f, d1 = 0.f, s2 = 0.f, d2 = 0.f;
    for (int k = 0; k < D; k++) {
        float w1 = W1[k * D + j], w2 = W2[k * D + j];
        s1 = fmaf(w1, a1s[k], s1); d1 = fmaf(w1, a1d[k], d1);
        s2 = fmaf(w2, a2s[k], s2); d2 = fmaf(w2, a2d[k], d2);
    }
    g_w1s[j] = s1; g_w1d[j] = d1; g_w2s[j] = s2; g_w2d[j] = d2;
}

// ---------------- dual register-tiled SGEMM (f32x2) --------------------------
// out[r,c] = act(bias[c] + in[r] . W[c,:]), two independent problems per grid.
__global__ __launch_bounds__(256, 2) void k_gemm2(
    const float* __restrict__ inA, const float* __restrict__ WA,
    const float* __restrict__ biasA, float* __restrict__ outA,
    const float* __restrict__ inB, const float* __restrict__ WB,
    const float* __restrict__ biasB, float* __restrict__ outB,
    int split, int rowsA, int rowsB, int relu)
{
    __shared__ float As[BK][BM];
    __shared__ float Bs[BK][128];

    const float *in, *W, *bias; float* out; int row0, nrows;
    if ((int)blockIdx.x < split) {
        in = inA; W = WA; bias = biasA; out = outA;
        row0 = blockIdx.x * BM; nrows = rowsA;
    } else {
        in = inB; W = WB; bias = biasB; out = outB;
        row0 = (blockIdx.x - split) * BM; nrows = rowsB;
    }

    const int tid = threadIdx.x;
    const int tr  = (tid >> 4) << 3;
    const int tc  = (tid & 15) << 3;

    unsigned long long acc[8][4];
    #pragma unroll
    for (int i = 0; i < 8; i++)
        #pragma unroll
        for (int j = 0; j < 4; j++) acc[i][j] = 0ull;

    for (int k0 = 0; k0 < D; k0 += BK) {
        __syncthreads();
        #pragma unroll
        for (int i = 0; i < 2; i++) {
            int lin = i * 256 + tid;
            int r   = lin >> 2;
            int jj  = (lin & 3) << 2;
            int gr  = row0 + r;
            float4 v = make_float4(0.f, 0.f, 0.f, 0.f);
            if (gr < nrows) v = *(const float4*)(in + (size_t)gr * D + k0 + jj);
            As[jj + 0][r] = v.x; As[jj + 1][r] = v.y;
            As[jj + 2][r] = v.z; As[jj + 3][r] = v.w;
            float4 w = *(const float4*)(W + (size_t)r * D + k0 + jj);
            Bs[jj + 0][r] = w.x; Bs[jj + 1][r] = w.y;
            Bs[jj + 2][r] = w.z; Bs[jj + 3][r] = w.w;
        }
        __syncthreads();

        #pragma unroll
        for (int kk = 0; kk < BK; kk++) {
            float4 a0 = *(const float4*)&As[kk][tr];
            float4 a1 = *(const float4*)&As[kk][tr + 4];
            ulonglong2 w0 = *(const ulonglong2*)&Bs[kk][tc];
            ulonglong2 w1 = *(const ulonglong2*)&Bs[kk][tc + 4];
            float a[8] = {a0.x, a0.y, a0.z, a0.w, a1.x, a1.y, a1.z, a1.w};
            #pragma unroll
            for (int i = 0; i < 8; i++) {
                unsigned long long ap = dup2(a[i]);
                ffma2(acc[i][0], ap, w0.x);
                ffma2(acc[i][1], ap, w0.y);
                ffma2(acc[i][2], ap, w1.x);
                ffma2(acc[i][3], ap, w1.y);
            }
        }
    }

    float bcol[8];
    #pragma unroll
    for (int j = 0; j < 8; j++) bcol[j] = bias ? bias[tc + j] : 0.f;

    #pragma unroll
    for (int i = 0; i < 8; i++) {
        int gr = row0 + tr + i;
        if (gr >= nrows) continue;
        float o[8];
        #pragma unroll
        for (int j = 0; j < 4; j++) {
            o[2 * j + 0] = __uint_as_float((unsigned)acc[i][j]) + bcol[2 * j + 0];
            o[2 * j + 1] = __uint_as_float((unsigned)(acc[i][j] >> 32)) + bcol[2 * j + 1];
        }
        if (relu) {
            #pragma unroll
            for (int j = 0; j < 8; j++) o[j] = fmaxf(o[j], 0.f);
        }
        *(float4*)(out + (size_t)gr * D + tc)     = make_float4(o[0], o[1], o[2], o[3]);
        *(float4*)(out + (size_t)gr * D + tc + 4) = make_float4(o[4], o[5], o[6], o[7]);
    }
}

// ---------------- attention logits: warp per node ---------------------------
__global__ void k_att() {
    int n = (blockIdx.x * blockDim.x + threadIdx.x) >> 5;
    int lane = threadIdx.x & 31;
    if (n >= NN) return;
    float4 xv = ((const float4*)g_x)[(size_t)n * 32 + lane];
    float4 w;
    w = ((const float4*)g_w1s)[lane];
    float p1 = xv.x * w.x + xv.y * w.y + xv.z * w.z + xv.w * w.w;
    w = ((const float4*)g_w1d)[lane];
    float p2 = xv.x * w.x + xv.y * w.y + xv.z * w.z + xv.w * w.w;
    w = ((const float4*)g_w2s)[lane];
    float p3 = xv.x * w.x + xv.y * w.y + xv.z * w.z + xv.w * w.w;
    w = ((const float4*)g_w2d)[lane];
    float p4 = xv.x * w.x + xv.y * w.y + xv.z * w.z + xv.w * w.w;
    #pragma unroll
    for (int off = 16; off; off >>= 1) {
        p1 += __shfl_down_sync(0xffffffffu, p1, off);
        p2 += __shfl_down_sync(0xffffffffu, p2, off);
        p3 += __shfl_down_sync(0xffffffffu, p3, off);
        p4 += __shfl_down_sync(0xffffffffu, p4, off);
    }
    if (lane == 0) { g_as1[n] = p1; g_ad1[n] = p2; g_as2[n] = p3; g_ad2[n] = p4; }
}

// ---------------- CSR pass 1: count edges per dst ----------------------------
__global__ void k_count(const void* __restrict__ idx, int dOff, int E,
                        int dAdd, int base) {
    int e = blockIdx.x * blockDim.x + threadIdx.x;
    if (e >= E) return;
    long long d; load_edge(idx, dOff, e, d);
    int di = (int)(d + dAdd) - base;
    if ((unsigned)di < (unsigned)HN) atomicAdd(&g_cnt[di], 1);
}

// ---------------- CSR pass 2: single-block exclusive scan --------------------
__global__ __launch_bounds__(1024) void k_scan() {
    __shared__ int wsum[32];
    int t = threadIdx.x, lane = t & 31, wid = t >> 5;
    int running = 0;
    for (int base = 0; base < HN; base += 1024) {
        int i = base + t;
        int v = (i < HN) ? g_cnt[i] : 0;
        int incl = v;
        #pragma unroll
        for (int o = 1; o < 32; o <<= 1) {
            int u = __shfl_up_sync(0xffffffffu, incl, o);
            if (lane >= o) incl += u;
        }
        if (lane == 31) wsum[wid] = incl;
        __syncthreads();
        if (wid == 0) {
            int s = wsum[lane];
            #pragma unroll
            for (int o = 1; o < 32; o <<= 1) {
                int u = __shfl_up_sync(0xffffffffu, s, o);
                if (lane >= o) s += u;
            }
            wsum[lane] = s;
        }
        __syncthreads();
        int woff = wid ? wsum[wid - 1] : 0;
        int excl = running + woff + incl - v;
        if (i < HN) { g_ptr[i] = excl; g_pos[i] = excl; }
        running += wsum[31];
        __syncthreads();
    }
    if (t == 0) g_ptr[HN] = running;
}

// ---------------- CSR pass 3: scatter (src, weight) --------------------------
__global__ void k_scatter(const void* __restrict__ idx, int sOff, int dOff, int E,
                          int sAdd, int dAdd, int base,
                          const float* __restrict__ as, const float* __restrict__ ad) {
    int e = blockIdx.x * blockDim.x + threadIdx.x;
    if (e >= E) return;
    long long s, d;
    load_edge(idx, sOff, e, s);
    load_edge(idx, dOff, e, d);
    int si = (int)(s + sAdd);
    int di = (int)(d + dAdd) - base;
    if ((unsigned)di >= (unsigned)HN) return;
    float w = __expf(lrelu(as[si] + ad[di + base]));
    int p = atomicAdd(&g_pos[di], 1);
    g_edge[p] = make_int2(si, __float_as_int(w));
}

// ---------------- aggregation: warp per dst, normalized output ---------------
__global__ void k_agg(int base, const float* __restrict__ as,
                      const float* __restrict__ ad, float* __restrict__ aggOut) {
    int i = (blockIdx.x * blockDim.x + threadIdx.x) >> 5;
    int lane = threadIdx.x & 31;
    if (i >= HN) return;
    int g = base + i;
    float w = __expf(lrelu(as[g] + ad[g]));        // self loop
    float denom = w;
    float4 xv = ((const float4*)g_x)[(size_t)g * 32 + lane];
    float4 acc = make_float4(xv.x * w, xv.y * w, xv.z * w, xv.w * w);
    int e0 = g_ptr[i], e1 = g_ptr[i + 1];
    for (int e = e0; e < e1; e++) {
        int2 ed = g_edge[e];                        // broadcast across warp
        float we = __int_as_float(ed.y);
        float4 xe = ((const float4*)g_x)[(size_t)ed.x * 32 + lane];
        acc.x = fmaf(xe.x, we, acc.x);
        acc.y = fmaf(xe.y, we, acc.y);
        acc.z = fmaf(xe.z, we, acc.z);
        acc.w = fmaf(xe.w, we, acc.w);
        denom += we;
    }
    float sc = 1.0f / (denom + 1e-16f);
    ((float4*)aggOut)[(size_t)i * 32 + lane] =
        make_float4(acc.x * sc, acc.y * sc, acc.z * sc, acc.w * sc);
}

// ---------------- driver ------------------------------------------------------
extern "C" void kernel_launch(void* const* d_in, const int* in_sizes, int n_in,
                              void* d_out, int out_size) {
    const void*  edge   = d_in[0];
    const void*  paper  = d_in[1];
    const void*  author = d_in[2];
    const float* x_s = (const float*)d_in[3];
    const float* x_t = (const float*)d_in[4];
    const float* Ws  = (const float*)d_in[5];
    const float* bs  = (const float*)d_in[6];
    const float* Wt  = (const float*)d_in[7];
    const float* bt  = (const float*)d_in[8];
    const float* W1  = (const float*)d_in[9];
    const float* a1s = (const float*)d_in[10];
    const float* a1d = (const float*)d_in[11];
    const float* W2  = (const float*)d_in[12];
    const float* a2s = (const float*)d_in[13];
    const float* a2d = (const float*)d_in[14];
    float* out = (float*)d_out;

    const int E0 = in_sizes[0] / 2;
    const int E1 = in_sizes[1] / 2;
    const int E2 = in_sizes[2] / 2;

    float* gx;    cudaGetSymbolAddress((void**)&gx,   g_x);
    float* gagg1; cudaGetSymbolAddress((void**)&gagg1, g_agg1);
    float* gagg2; cudaGetSymbolAddress((void**)&gagg2, g_agg2);
    float *gas1, *gad1, *gas2, *gad2;
    cudaGetSymbolAddress((void**)&gas1, g_as1);
    cudaGetSymbolAddress((void**)&gad1, g_ad1);
    cudaGetSymbolAddress((void**)&gas2, g_as2);
    cudaGetSymbolAddress((void**)&gad2, g_ad2);
    int* gcnt; cudaGetSymbolAddress((void**)&gcnt, g_cnt);

    const int GB = (NS + BM - 1) / BM;      // 391 blocks per 50K-row GEMM
    const int TB = 256;
    const int EB0 = (E0 + TB - 1) / TB;
    const int EB1 = (E1 + TB - 1) / TB;
    const int EB2 = (E2 + TB - 1) / TB;
    const int WNB = (HN * 32 + TB - 1) / TB;
    const int ATTB = (NN * 32 + TB - 1) / TB;

    k_detect<<<1, 32>>>((const int*)edge);
    k_wvec<<<1, 128>>>(W1, a1s, a1d, W2, a2s, a2d);

    // fused input transforms: g_x = [x_s@Ws^T+bs ; x_t@Wt^T+bt]
    k_gemm2<<<2 * GB, 256>>>(x_s, Ws, bs, gx,
                             x_t, Wt, bt, gx + (size_t)NS * D,
                             GB, NS, NT, 0);
    k_att<<<ATTB, TB>>>();

    // ---- conv1: dst in [NS, NN) ----
    cudaMemsetAsync(gcnt, 0, HN * sizeof(int));
    k_count<<<EB0, TB>>>(edge,   E0, E0, NS, NS);
    k_count<<<EB2, TB>>>(author, E2, E2, 0,  NS);
    k_scan<<<1, 1024>>>();
    k_scatter<<<EB0, TB>>>(edge,   0, E0, E0, 0, NS, NS, gas1, gad1);
    k_scatter<<<EB2, TB>>>(author, 0, E2, E2, 0, 0,  NS, gas1, gad1);
    k_agg<<<WNB, TB>>>(NS, gas1, gad1, gagg1);

    // ---- conv2: dst in [0, NS) ----
    cudaMemsetAsync(gcnt, 0, HN * sizeof(int));
    k_count<<<EB0, TB>>>(edge,  0,  E0, 0, 0);
    k_count<<<EB1, TB>>>(paper, E1, E1, 0, 0);
    k_scan<<<1, 1024>>>();
    k_scatter<<<EB0, TB>>>(edge,  E0, 0,  E0, NS, 0, 0, gas2, gad2);
    k_scatter<<<EB1, TB>>>(paper, 0,  E1, E1, 0,  0, 0, gas2, gad2);
    k_agg<<<WNB, TB>>>(0, gas2, gad2, gagg2);

    // fused output GEMMs: out[NS:] = relu(agg1@W1^T), out[:NS] = relu(agg2@W2^T)
    k_gemm2<<<2 * GB, 256>>>(gagg1, W1, nullptr, out + (size_t)NS * D,
                             gagg2, W2, nullptr, out,
                             GB, NS, NS, 1);
}